// round 7
// baseline (speedup 1.0000x reference)
#include <cuda_runtime.h>
#include <cuda_bf16.h>
#include <math.h>
#include <stdint.h>

// LiquidNCPNetwork via warp-level bf16 mma.sync + split-K partials.
// Per (cell, step): D[128][128] = A[128][Kc] @ B[128][Kc]^T per 16-col tile,
// K split over ksplit blocks; last-arriving block combines partials (fixed
// order -> deterministic) and applies the CfC gating epilogue.
//   A rows 0-63 = z_hi (batch), rows 64-127 = z_lo.
//   B row n = jj*8 + head*2 + part  (part 0 = W_hi, 1 = W_lo), K-major bf16.
//   out(b,jj,head) = D[b][2h] + D[b][2h+1] + D[b+64][2h]   (drop lo*lo).

#define BATCH  64
#define SEQ    32
#define IN_F   512
#define INTER  1229
#define CMD    819
#define MOTOR  512
#define NUNITS 2560
#define YSZ    (BATCH * SEQ * MOTOR)

#define HPAD1 1280
#define KC1   1792
#define XCH1  8
#define HCH1  20
#define XPAD2 1280
#define HPAD2 832
#define KC2   2112
#define XCH2  20
#define HCH2  13
#define XPAD3 832
#define HPAD3 512
#define KC3   1344
#define XCH3  13
#define HCH3  8
#define JT1 77
#define JT2 52
#define JT3 32
#define KSPL1 2
#define KSPL2 3
#define KSPL3 4

__device__ __align__(1024) __nv_bfloat16 g_wb1[(size_t)JT1 * 128 * KC1];
__device__ __align__(1024) __nv_bfloat16 g_wb2[(size_t)JT2 * 128 * KC2];
__device__ __align__(1024) __nv_bfloat16 g_wb3[(size_t)JT3 * 128 * KC3];
__device__ __align__(1024) __nv_bfloat16 g_x1[(size_t)SEQ * 128 * IN_F];
__device__ __align__(1024) __nv_bfloat16 g_z1h[2][128 * HPAD1];
__device__ __align__(1024) __nv_bfloat16 g_z2x[128 * XPAD2];
__device__ __align__(1024) __nv_bfloat16 g_z2h[2][128 * HPAD2];
__device__ __align__(1024) __nv_bfloat16 g_z3x[128 * XPAD3];
__device__ __align__(1024) __nv_bfloat16 g_z3h[2][128 * HPAD3];
// split-K partials: [tile][split][128][64] f32, and arrival counters
__device__ __align__(16) float g_part[(size_t)JT1 * 4 * 128 * 64];
__device__ int g_cnt[SEQ * 3 * JT1];

#define SW128(o) ((o) ^ (((o) >> 3) & 0x70))
#define STAGE_BYTES 32768
#define SMEM_TOTAL  (3 * STAGE_BYTES)

__device__ __forceinline__ uint32_t s2u32(const void* p) {
    uint32_t a;
    asm("{ .reg .u64 t; cvta.to.shared.u64 t, %1; cvt.u32.u64 %0, t; }" : "=r"(a) : "l"(p));
    return a;
}
__device__ __forceinline__ void cpasync16(uint32_t s, const void* g) {
    asm volatile("cp.async.cg.shared.global [%0], [%1], 16;" :: "r"(s), "l"(g));
}
template<int N> __device__ __forceinline__ void waitgrp() {
    asm volatile("cp.async.wait_group %0;" :: "n"(N) : "memory");
}
__device__ __forceinline__ void ldm_x4(uint32_t& r0, uint32_t& r1, uint32_t& r2,
                                       uint32_t& r3, uint32_t addr) {
    asm volatile("ldmatrix.sync.aligned.m8n8.x4.shared.b16 {%0,%1,%2,%3}, [%4];"
                 : "=r"(r0), "=r"(r1), "=r"(r2), "=r"(r3) : "r"(addr));
}
__device__ __forceinline__ void mma16816(float* c, uint32_t a0, uint32_t a1, uint32_t a2,
                                         uint32_t a3, uint32_t b0, uint32_t b1) {
    asm volatile("mma.sync.aligned.m16n8k16.row.col.f32.bf16.bf16.f32 "
                 "{%0,%1,%2,%3}, {%4,%5,%6,%7}, {%8,%9}, {%0,%1,%2,%3};"
                 : "+f"(c[0]), "+f"(c[1]), "+f"(c[2]), "+f"(c[3])
                 : "r"(a0), "r"(a1), "r"(a2), "r"(a3), "r"(b0), "r"(b1));
}

// ---------------- prep kernels ----------------
__global__ void init_cnt_kernel() {
    int i = blockIdx.x * 256 + threadIdx.x;
    if (i < SEQ * 3 * JT1) g_cnt[i] = 0;
}

__global__ void prep_w_kernel(const float* __restrict__ Wg, const float* __restrict__ Wh,
                              const float* __restrict__ Wfg, const float* __restrict__ Wfh,
                              const float* __restrict__ M, __nv_bfloat16* __restrict__ dst,
                              int N, int Korig, int xvalid, int xpad, int hvalid, int Kc)
{
    int n = blockIdx.x * 2;
    int loc = n & 127;
    int j = (n >> 7) * 16 + (loc >> 3);
    int t = (loc >> 1) & 3;
    const float* W = (t == 0) ? Wg : (t == 1) ? Wh : (t == 2) ? Wfg : Wfh;
    __nv_bfloat16* d_hi = dst + (size_t)n * Kc;
    __nv_bfloat16* d_lo = d_hi + Kc;
    bool jok = (j < N);
    for (int k = threadIdx.x; k < Kc; k += 256) {
        float v = 0.f;
        if (jok) {
            int kin; bool ok;
            if (k < xpad) { kin = k; ok = (k < xvalid); }
            else { int hk = k - xpad; kin = xvalid + hk; ok = (hk < hvalid); }
            if (ok) v = W[(size_t)j * Korig + kin] * M[(size_t)j * Korig + kin];
        }
        __nv_bfloat16 hi = __float2bfloat16(v);
        d_hi[k] = hi;
        d_lo[k] = __float2bfloat16(v - __bfloat162float(hi));
    }
}

__global__ void prep_x_kernel(const float* __restrict__ x, __nv_bfloat16* __restrict__ dst)
{
    int idx = blockIdx.x * 256 + threadIdx.x;
    int b = idx >> 14, r = idx & 16383, s = r >> 9, f = r & 511;
    float v = x[idx];
    __nv_bfloat16 hi = __float2bfloat16(v);
    size_t base = (size_t)s * 128 * 512;
    dst[base + (size_t)b * 512 + f] = hi;
    dst[base + (size_t)(b + 64) * 512 + f] = __float2bfloat16(v - __bfloat162float(hi));
}

__global__ void prep_h0_kernel(const float* __restrict__ h0, __nv_bfloat16* __restrict__ z1,
                               __nv_bfloat16* __restrict__ z2, __nv_bfloat16* __restrict__ z3)
{
    int idx = blockIdx.x * 256 + threadIdx.x;
    int b = idx / NUNITS, u = idx % NUNITS;
    float v = h0[idx];
    __nv_bfloat16 hi = __float2bfloat16(v);
    __nv_bfloat16 lo = __float2bfloat16(v - __bfloat162float(hi));
    if (u < INTER)            { z1[(size_t)b*HPAD1+u] = hi; z1[(size_t)(b+64)*HPAD1+u] = lo; }
    else if (u < INTER + CMD) { int c = u - INTER;
                                z2[(size_t)b*HPAD2+c] = hi; z2[(size_t)(b+64)*HPAD2+c] = lo; }
    else                      { int c = u - INTER - CMD;
                                z3[(size_t)b*HPAD3+c] = hi; z3[(size_t)(b+64)*HPAD3+c] = lo; }
}

// ---------------- cell kernel (warp mma + split-K) ----------------
__global__ void __launch_bounds__(256, 2)
cell_mma_kernel(
    const __nv_bfloat16* __restrict__ xpart, int xstride, int xchunks,
    const __nv_bfloat16* __restrict__ hpart, int hstride, int hchunks,
    const __nv_bfloat16* __restrict__ wbase, int wKc,
    const float* __restrict__ bg, const float* __restrict__ bh,
    const float* __restrict__ bfg, const float* __restrict__ bfh,
    const float* __restrict__ tsp, int sidx, int cellid, int ksplit, int N,
    __nv_bfloat16* __restrict__ znx, int znx_stride,
    __nv_bfloat16* __restrict__ zsh, int zsh_stride,
    float* __restrict__ yp, float* __restrict__ hfp, int hoff)
{
    extern __shared__ char smem[];
    const int tid  = threadIdx.x;
    const int lane = tid & 31;
    const int wid  = tid >> 5;
    const int warprow = wid >> 2;          // 0 = hi rows, 1 = lo rows
    const int warpcol = wid & 3;
    const int m_warp = warprow * 64;
    const int n_warp = warpcol * 32;
    const uint32_t sb = s2u32(smem);
    const int tile  = blockIdx.x;
    const int split = blockIdx.y;
    const int C = xchunks + hchunks;
    const int c0 = (C * split) / ksplit;
    const int c1 = (C * (split + 1)) / ksplit;

    float acc[4][4][4];
    #pragma unroll
    for (int mt = 0; mt < 4; mt++)
        #pragma unroll
        for (int nt = 0; nt < 4; nt++)
            #pragma unroll
            for (int i = 0; i < 4; i++) acc[mt][nt][i] = 0.f;

    auto load_stage = [&](int c) {
        uint32_t abase = sb + (uint32_t)(c % 3) * STAGE_BYTES;
        uint32_t bbase = abase + 16384;
        const char* asrc; size_t astr;
        if (c < xchunks) { asrc = (const char*)xpart + (size_t)c * 128; astr = (size_t)xstride * 2; }
        else { asrc = (const char*)hpart + (size_t)(c - xchunks) * 128; astr = (size_t)hstride * 2; }
        const char* bsrc = (const char*)wbase
                         + ((size_t)tile * 128 * wKc + (size_t)c * 64) * 2;
        const size_t bstr = (size_t)wKc * 2;
        #pragma unroll
        for (int i = 0; i < 4; i++) {
            int g = i * 256 + tid;
            int row = g >> 3, col = g & 7;
            uint32_t off = (uint32_t)(row * 128 + col * 16);
            cpasync16(abase + SW128(off), asrc + (size_t)row * astr + col * 16);
            cpasync16(bbase + SW128(off), bsrc + (size_t)row * bstr + col * 16);
        }
        asm volatile("cp.async.commit_group;" ::: "memory");
    };

    load_stage(c0);
    if (c0 + 1 < c1) load_stage(c0 + 1);

    for (int c = c0; c < c1; c++) {
        if (c + 2 < c1) { load_stage(c + 2); waitgrp<2>(); }
        else if (c + 1 < c1) waitgrp<1>();
        else waitgrp<0>();
        __syncthreads();

        uint32_t abase = sb + (uint32_t)(c % 3) * STAGE_BYTES;
        uint32_t bbase = abase + 16384;
        #pragma unroll
        for (int ks = 0; ks < 4; ks++) {
            int kb = ks * 32 + (lane >> 4) * 16;
            uint32_t af[4][4];
            #pragma unroll
            for (int mt = 0; mt < 4; mt++) {
                uint32_t off = (uint32_t)((m_warp + mt * 16 + (lane & 15)) * 128 + kb);
                ldm_x4(af[mt][0], af[mt][1], af[mt][2], af[mt][3], abase + SW128(off));
            }
            uint32_t bf[4][2];
            #pragma unroll
            for (int np = 0; np < 2; np++) {
                uint32_t off = (uint32_t)((n_warp + np * 16 + (lane & 15)) * 128 + kb);
                uint32_t r0, r1, r2, r3;
                ldm_x4(r0, r1, r2, r3, bbase + SW128(off));
                bf[np * 2][0] = r0; bf[np * 2 + 1][0] = r1;
                bf[np * 2][1] = r2; bf[np * 2 + 1][1] = r3;
            }
            #pragma unroll
            for (int mt = 0; mt < 4; mt++)
                #pragma unroll
                for (int nt = 0; nt < 4; nt++)
                    mma16816(acc[mt][nt], af[mt][0], af[mt][1], af[mt][2], af[mt][3],
                             bf[nt][0], bf[nt][1]);
        }
        __syncthreads();
    }

    // write this split's partial P[128][64]: hi rows = c(2t)+c(2t+1), lo rows = c(2t)
    float* P = g_part + ((size_t)tile * 4 + split) * (128 * 64);
    {
        int hrow = lane >> 2, head = lane & 3;
        #pragma unroll
        for (int mt = 0; mt < 4; mt++) {
            #pragma unroll
            for (int nt = 0; nt < 4; nt++) {
                int col = (warpcol * 4 + nt) * 4 + head;
                int r0 = m_warp + mt * 16 + hrow;
                if (warprow == 0) {
                    P[r0 * 64 + col] = acc[mt][nt][0] + acc[mt][nt][1];
                    P[(r0 + 8) * 64 + col] = acc[mt][nt][2] + acc[mt][nt][3];
                } else {
                    P[r0 * 64 + col] = acc[mt][nt][0];
                    P[(r0 + 8) * 64 + col] = acc[mt][nt][2];
                }
            }
        }
    }
    __threadfence();
    __syncthreads();

    __shared__ int s_last;
    if (tid == 0) {
        int prev = atomicAdd(&g_cnt[(sidx * 3 + cellid) * JT1 + tile], 1);
        s_last = (prev == ksplit - 1);
    }
    __syncthreads();
    if (!s_last) return;
    __threadfence();   // acquire: make other splits' partials visible

    // combine splits in fixed index order (deterministic) + gating epilogue
    const float* Pb = g_part + (size_t)tile * 4 * (128 * 64);
    const float ts = tsp[sidx];
    #pragma unroll
    for (int it = 0; it < 4; it++) {
        int pair = tid + it * 256;          // 0..1023
        int b = pair >> 4;
        int jj = pair & 15;
        int j = tile * 16 + jj;
        if (j >= N) continue;
        float4 h4 = make_float4(0.f, 0.f, 0.f, 0.f);
        float4 l4 = make_float4(0.f, 0.f, 0.f, 0.f);
        for (int s = 0; s < ksplit; s++) {
            const float4* Ph = (const float4*)(Pb + (size_t)s * (128 * 64) + b * 64 + jj * 4);
            const float4* Pl = (const float4*)(Pb + (size_t)s * (128 * 64) + (b + 64) * 64 + jj * 4);
            float4 a = *Ph, c = *Pl;
            h4.x += a.x; h4.y += a.y; h4.z += a.z; h4.w += a.w;
            l4.x += c.x; l4.y += c.y; l4.z += c.z; l4.w += c.w;
        }
        float a0 = h4.x + l4.x;
        float a1 = h4.y + l4.y;
        float a2 = h4.z + l4.z;
        float a3 = h4.w + l4.w;
        float g    = tanhf(a0 + bg[j]);
        float hh   = tanhf(a1 + bh[j]);
        float pre  = (a2 + bfg[j]) + ts * (a3 + bfh[j]);
        float gate = 1.f / (1.f + expf(-pre));
        float o    = g * (1.f - gate) + hh * gate;
        __nv_bfloat16 ohi = __float2bfloat16(o);
        __nv_bfloat16 olo = __float2bfloat16(o - __bfloat162float(ohi));
        if (znx) {
            znx[(size_t)b * znx_stride + j] = ohi;
            znx[(size_t)(b + 64) * znx_stride + j] = olo;
        }
        zsh[(size_t)b * zsh_stride + j] = ohi;
        zsh[(size_t)(b + 64) * zsh_stride + j] = olo;
        if (yp)  yp[(size_t)b * (SEQ * MOTOR) + j] = o;
        if (hfp) hfp[(size_t)b * NUNITS + hoff + j] = o;
    }
}

// ---------------- host ----------------
extern "C" void kernel_launch(void* const* d_in, const int* in_sizes, int n_in,
                              void* d_out, int out_size)
{
    const float* x   = (const float*)d_in[0];
    const float* h0  = (const float*)d_in[1];
    const float* ts  = (const float*)d_in[2];
    const float *Wg1=(const float*)d_in[3], *Wh1=(const float*)d_in[4],
                *Wfg1=(const float*)d_in[5], *Wfh1=(const float*)d_in[6],
                *bg1=(const float*)d_in[7], *bh1=(const float*)d_in[8],
                *bfg1=(const float*)d_in[9], *bfh1=(const float*)d_in[10],
                *m1=(const float*)d_in[11];
    const float *Wg2=(const float*)d_in[12], *Wh2=(const float*)d_in[13],
                *Wfg2=(const float*)d_in[14], *Wfh2=(const float*)d_in[15],
                *bg2=(const float*)d_in[16], *bh2=(const float*)d_in[17],
                *bfg2=(const float*)d_in[18], *bfh2=(const float*)d_in[19],
                *m2=(const float*)d_in[20];
    const float *Wg3=(const float*)d_in[21], *Wh3=(const float*)d_in[22],
                *Wfg3=(const float*)d_in[23], *Wfh3=(const float*)d_in[24],
                *bg3=(const float*)d_in[25], *bh3=(const float*)d_in[26],
                *bfg3=(const float*)d_in[27], *bfh3=(const float*)d_in[28],
                *m3=(const float*)d_in[29];
    float* out = (float*)d_out;

    __nv_bfloat16 *wb1, *wb2, *wb3, *x1, *z1h, *z2x, *z2h, *z3x, *z3h;
    cudaGetSymbolAddress((void**)&wb1, g_wb1);
    cudaGetSymbolAddress((void**)&wb2, g_wb2);
    cudaGetSymbolAddress((void**)&wb3, g_wb3);
    cudaGetSymbolAddress((void**)&x1,  g_x1);
    cudaGetSymbolAddress((void**)&z1h, g_z1h);
    cudaGetSymbolAddress((void**)&z2x, g_z2x);
    cudaGetSymbolAddress((void**)&z2h, g_z2h);
    cudaGetSymbolAddress((void**)&z3x, g_z3x);
    cudaGetSymbolAddress((void**)&z3h, g_z3h);

    cudaFuncSetAttribute(cell_mma_kernel, cudaFuncAttributeMaxDynamicSharedMemorySize,
                         SMEM_TOTAL);

    init_cnt_kernel<<<(SEQ * 3 * JT1 + 255) / 256, 256>>>();
    prep_w_kernel<<<JT1 * 64, 256>>>(Wg1, Wh1, Wfg1, Wfh1, m1, wb1,
                                     INTER, IN_F + INTER, IN_F, IN_F, INTER, KC1);
    prep_w_kernel<<<JT2 * 64, 256>>>(Wg2, Wh2, Wfg2, Wfh2, m2, wb2,
                                     CMD, INTER + CMD, INTER, XPAD2, CMD, KC2);
    prep_w_kernel<<<JT3 * 64, 256>>>(Wg3, Wh3, Wfg3, Wfh3, m3, wb3,
                                     MOTOR, CMD + MOTOR, CMD, XPAD3, MOTOR, KC3);
    prep_x_kernel<<<(BATCH * SEQ * IN_F) / 256, 256>>>(x, x1);
    prep_h0_kernel<<<(BATCH * NUNITS) / 256, 256>>>(h0, z1h, z2h, z3h);

    int p = 0;
    for (int s = 0; s < SEQ; s++) {
        const __nv_bfloat16* xt = x1 + (size_t)s * 128 * IN_F;
        float* hfp = (s == SEQ - 1) ? (out + YSZ) : nullptr;
        cell_mma_kernel<<<dim3(JT1, KSPL1), 256, SMEM_TOTAL>>>(
            xt, IN_F, XCH1, z1h + (size_t)p * 128 * HPAD1, HPAD1, HCH1,
            wb1, KC1, bg1, bh1, bfg1, bfh1, ts, s, 0, KSPL1, INTER,
            z2x, XPAD2, z1h + (size_t)(1 - p) * 128 * HPAD1, HPAD1,
            nullptr, hfp, 0);
        cell_mma_kernel<<<dim3(JT2, KSPL2), 256, SMEM_TOTAL>>>(
            z2x, XPAD2, XCH2, z2h + (size_t)p * 128 * HPAD2, HPAD2, HCH2,
            wb2, KC2, bg2, bh2, bfg2, bfh2, ts, s, 1, KSPL2, CMD,
            z3x, XPAD3, z2h + (size_t)(1 - p) * 128 * HPAD2, HPAD2,
            nullptr, hfp, INTER);
        cell_mma_kernel<<<dim3(JT3, KSPL3), 256, SMEM_TOTAL>>>(
            z3x, XPAD3, XCH3, z3h + (size_t)p * 128 * HPAD3, HPAD3, HCH3,
            wb3, KC3, bg3, bh3, bfg3, bfh3, ts, s, 2, KSPL3, MOTOR,
            nullptr, 0, z3h + (size_t)(1 - p) * 128 * HPAD3, HPAD3,
            out + (size_t)s * MOTOR, hfp, INTER + CMD);
        p ^= 1;
    }
}

// round 8
// speedup vs baseline: 1.2766x; 1.2766x over previous
#include <cuda_runtime.h>
#include <cuda_bf16.h>
#include <math.h>
#include <stdint.h>

// LiquidNCPNetwork: single persistent kernel for the full 32-step scan.
// 148 blocks x 256 threads, 1 block/SM (96KB smem) -> all co-resident, so a
// software grid barrier is safe. 96 phases: per (step, cell) compute split-K
// partials -> barrier -> combine (fixed order, deterministic) + CfC gating
// -> barrier. Math identical to R6/R7 (bf16 hi/lo split, drop lo*lo term).

#define BATCH  64
#define SEQ    32
#define IN_F   512
#define INTER  1229
#define CMD    819
#define MOTOR  512
#define NUNITS 2560
#define YSZ    (BATCH * SEQ * MOTOR)

#define HPAD1 1280
#define KC1   1792
#define XCH1  8
#define HCH1  20
#define XPAD2 1280
#define HPAD2 832
#define KC2   2112
#define XCH2  20
#define HCH2  13
#define XPAD3 832
#define HPAD3 512
#define KC3   1344
#define XCH3  13
#define HCH3  8
#define JT1 77
#define JT2 52
#define JT3 32

#define GRID 148
#define KS   4          // split-K factor, all cells

__device__ __align__(1024) __nv_bfloat16 g_wb1[(size_t)JT1 * 128 * KC1];
__device__ __align__(1024) __nv_bfloat16 g_wb2[(size_t)JT2 * 128 * KC2];
__device__ __align__(1024) __nv_bfloat16 g_wb3[(size_t)JT3 * 128 * KC3];
__device__ __align__(1024) __nv_bfloat16 g_x1[(size_t)SEQ * 128 * IN_F];
__device__ __align__(1024) __nv_bfloat16 g_z1h[2][128 * HPAD1];
__device__ __align__(1024) __nv_bfloat16 g_z2x[128 * XPAD2];
__device__ __align__(1024) __nv_bfloat16 g_z2h[2][128 * HPAD2];
__device__ __align__(1024) __nv_bfloat16 g_z3x[128 * XPAD3];
__device__ __align__(1024) __nv_bfloat16 g_z3h[2][128 * HPAD3];
// split-K partials: [tile][split][128][64] f32
__device__ __align__(16) float g_part[(size_t)JT1 * KS * 128 * 64];
// grid barrier state (reset by reset_kernel after the scan)
__device__ volatile int g_flags[GRID * 8];   // one 32B slot per block
__device__ volatile int g_release;

#define SW128(o) ((o) ^ (((o) >> 3) & 0x70))
#define STAGE_BYTES 32768
#define SMEM_TOTAL  (3 * STAGE_BYTES)

__device__ __forceinline__ uint32_t s2u32(const void* p) {
    uint32_t a;
    asm("{ .reg .u64 t; cvta.to.shared.u64 t, %1; cvt.u32.u64 %0, t; }" : "=r"(a) : "l"(p));
    return a;
}
__device__ __forceinline__ void cpasync16(uint32_t s, const void* g) {
    asm volatile("cp.async.cg.shared.global [%0], [%1], 16;" :: "r"(s), "l"(g));
}
template<int N> __device__ __forceinline__ void waitgrp() {
    asm volatile("cp.async.wait_group %0;" :: "n"(N) : "memory");
}
__device__ __forceinline__ void ldm_x4(uint32_t& r0, uint32_t& r1, uint32_t& r2,
                                       uint32_t& r3, uint32_t addr) {
    asm volatile("ldmatrix.sync.aligned.m8n8.x4.shared.b16 {%0,%1,%2,%3}, [%4];"
                 : "=r"(r0), "=r"(r1), "=r"(r2), "=r"(r3) : "r"(addr));
}
__device__ __forceinline__ void mma16816(float* c, uint32_t a0, uint32_t a1, uint32_t a2,
                                         uint32_t a3, uint32_t b0, uint32_t b1) {
    asm volatile("mma.sync.aligned.m16n8k16.row.col.f32.bf16.bf16.f32 "
                 "{%0,%1,%2,%3}, {%4,%5,%6,%7}, {%8,%9}, {%0,%1,%2,%3};"
                 : "+f"(c[0]), "+f"(c[1]), "+f"(c[2]), "+f"(c[3])
                 : "r"(a0), "r"(a1), "r"(a2), "r"(a3), "r"(b0), "r"(b1));
}

// grid barrier: per-block flag slots + leader (block 0) release. Monotonic
// targets; state restored to 0 by reset_kernel after the scan completes.
__device__ __forceinline__ void gbar(int bid, int tid, int target) {
    __threadfence();
    __syncthreads();
    if (bid == 0) {
        if (tid == 0) g_flags[0] = target;
        if (tid < GRID) {
            while (g_flags[tid * 8] < target) __nanosleep(64);
        }
        __syncthreads();
        if (tid == 0) g_release = target;
        __syncthreads();
    } else {
        if (tid == 0) {
            g_flags[bid * 8] = target;
            while (g_release < target) __nanosleep(64);
        }
        __syncthreads();
    }
}

// ---------------- prep kernels ----------------
__global__ void prep_w_kernel(const float* __restrict__ Wg, const float* __restrict__ Wh,
                              const float* __restrict__ Wfg, const float* __restrict__ Wfh,
                              const float* __restrict__ M, __nv_bfloat16* __restrict__ dst,
                              int N, int Korig, int xvalid, int xpad, int hvalid, int Kc)
{
    int n = blockIdx.x * 2;
    int loc = n & 127;
    int j = (n >> 7) * 16 + (loc >> 3);
    int t = (loc >> 1) & 3;
    const float* W = (t == 0) ? Wg : (t == 1) ? Wh : (t == 2) ? Wfg : Wfh;
    __nv_bfloat16* d_hi = dst + (size_t)n * Kc;
    __nv_bfloat16* d_lo = d_hi + Kc;
    bool jok = (j < N);
    for (int k = threadIdx.x; k < Kc; k += 256) {
        float v = 0.f;
        if (jok) {
            int kin; bool ok;
            if (k < xpad) { kin = k; ok = (k < xvalid); }
            else { int hk = k - xpad; kin = xvalid + hk; ok = (hk < hvalid); }
            if (ok) v = W[(size_t)j * Korig + kin] * M[(size_t)j * Korig + kin];
        }
        __nv_bfloat16 hi = __float2bfloat16(v);
        d_hi[k] = hi;
        d_lo[k] = __float2bfloat16(v - __bfloat162float(hi));
    }
}

__global__ void prep_x_kernel(const float* __restrict__ x, __nv_bfloat16* __restrict__ dst)
{
    int idx = blockIdx.x * 256 + threadIdx.x;
    int b = idx >> 14, r = idx & 16383, s = r >> 9, f = r & 511;
    float v = x[idx];
    __nv_bfloat16 hi = __float2bfloat16(v);
    size_t base = (size_t)s * 128 * 512;
    dst[base + (size_t)b * 512 + f] = hi;
    dst[base + (size_t)(b + 64) * 512 + f] = __float2bfloat16(v - __bfloat162float(hi));
}

__global__ void prep_h0_kernel(const float* __restrict__ h0, __nv_bfloat16* __restrict__ z1,
                               __nv_bfloat16* __restrict__ z2, __nv_bfloat16* __restrict__ z3)
{
    int idx = blockIdx.x * 256 + threadIdx.x;
    int b = idx / NUNITS, u = idx % NUNITS;
    float v = h0[idx];
    __nv_bfloat16 hi = __float2bfloat16(v);
    __nv_bfloat16 lo = __float2bfloat16(v - __bfloat162float(hi));
    if (u < INTER)            { z1[(size_t)b*HPAD1+u] = hi; z1[(size_t)(b+64)*HPAD1+u] = lo; }
    else if (u < INTER + CMD) { int c = u - INTER;
                                z2[(size_t)b*HPAD2+c] = hi; z2[(size_t)(b+64)*HPAD2+c] = lo; }
    else                      { int c = u - INTER - CMD;
                                z3[(size_t)b*HPAD3+c] = hi; z3[(size_t)(b+64)*HPAD3+c] = lo; }
}

__global__ void reset_kernel() {
    int i = threadIdx.x;
    if (i < GRID * 8) g_flags[i] = 0;
    if (i == 0) g_release = 0;
}

// ---------------- persistent scan kernel ----------------
__device__ __forceinline__ void compute_partial(
    uint32_t sb, int tid,
    const __nv_bfloat16* xpart, int xstride, int xchunks,
    const __nv_bfloat16* hpart, int hstride, int hchunks,
    const __nv_bfloat16* wbase, int wKc,
    int tile, int split)
{
    const int lane = tid & 31;
    const int wid  = tid >> 5;
    const int warprow = wid >> 2;
    const int warpcol = wid & 3;
    const int m_warp = warprow * 64;
    const int n_warp = warpcol * 32;
    const int C = xchunks + hchunks;
    const int c0 = (C * split) / KS;
    const int c1 = (C * (split + 1)) / KS;

    float acc[4][4][4];
    #pragma unroll
    for (int mt = 0; mt < 4; mt++)
        #pragma unroll
        for (int nt = 0; nt < 4; nt++)
            #pragma unroll
            for (int i = 0; i < 4; i++) acc[mt][nt][i] = 0.f;

    auto load_stage = [&](int c) {
        uint32_t abase = sb + (uint32_t)(c % 3) * STAGE_BYTES;
        uint32_t bbase = abase + 16384;
        const char* asrc; size_t astr;
        if (c < xchunks) { asrc = (const char*)xpart + (size_t)c * 128; astr = (size_t)xstride * 2; }
        else { asrc = (const char*)hpart + (size_t)(c - xchunks) * 128; astr = (size_t)hstride * 2; }
        const char* bsrc = (const char*)wbase
                         + ((size_t)tile * 128 * wKc + (size_t)c * 64) * 2;
        const size_t bstr = (size_t)wKc * 2;
        #pragma unroll
        for (int i = 0; i < 4; i++) {
            int g = i * 256 + tid;
            int row = g >> 3, col = g & 7;
            uint32_t off = (uint32_t)(row * 128 + col * 16);
            cpasync16(abase + SW128(off), asrc + (size_t)row * astr + col * 16);
            cpasync16(bbase + SW128(off), bsrc + (size_t)row * bstr + col * 16);
        }
        asm volatile("cp.async.commit_group;" ::: "memory");
    };

    load_stage(c0);
    if (c0 + 1 < c1) load_stage(c0 + 1);

    for (int c = c0; c < c1; c++) {
        if (c + 2 < c1) { load_stage(c + 2); waitgrp<2>(); }
        else if (c + 1 < c1) waitgrp<1>();
        else waitgrp<0>();
        __syncthreads();

        uint32_t abase = sb + (uint32_t)(c % 3) * STAGE_BYTES;
        uint32_t bbase = abase + 16384;
        #pragma unroll
        for (int ks = 0; ks < 4; ks++) {
            int kb = ks * 32 + (lane >> 4) * 16;
            uint32_t af[4][4];
            #pragma unroll
            for (int mt = 0; mt < 4; mt++) {
                uint32_t off = (uint32_t)((m_warp + mt * 16 + (lane & 15)) * 128 + kb);
                ldm_x4(af[mt][0], af[mt][1], af[mt][2], af[mt][3], abase + SW128(off));
            }
            uint32_t bf[4][2];
            #pragma unroll
            for (int np = 0; np < 2; np++) {
                uint32_t off = (uint32_t)((n_warp + np * 16 + (lane & 15)) * 128 + kb);
                uint32_t r0, r1, r2, r3;
                ldm_x4(r0, r1, r2, r3, bbase + SW128(off));
                bf[np * 2][0] = r0; bf[np * 2 + 1][0] = r1;
                bf[np * 2][1] = r2; bf[np * 2 + 1][1] = r3;
            }
            #pragma unroll
            for (int mt = 0; mt < 4; mt++)
                #pragma unroll
                for (int nt = 0; nt < 4; nt++)
                    mma16816(acc[mt][nt], af[mt][0], af[mt][1], af[mt][2], af[mt][3],
                             bf[nt][0], bf[nt][1]);
        }
        __syncthreads();
    }

    // partial P[128][64]: hi rows = c(2t)+c(2t+1), lo rows = c(2t)
    float* P = g_part + ((size_t)tile * KS + split) * (128 * 64);
    int hrow = lane >> 2, head = lane & 3;
    #pragma unroll
    for (int mt = 0; mt < 4; mt++) {
        #pragma unroll
        for (int nt = 0; nt < 4; nt++) {
            int col = (warpcol * 4 + nt) * 4 + head;
            int r0 = m_warp + mt * 16 + hrow;
            if (warprow == 0) {
                P[r0 * 64 + col] = acc[mt][nt][0] + acc[mt][nt][1];
                P[(r0 + 8) * 64 + col] = acc[mt][nt][2] + acc[mt][nt][3];
            } else {
                P[r0 * 64 + col] = acc[mt][nt][0];
                P[(r0 + 8) * 64 + col] = acc[mt][nt][2];
            }
        }
    }
}

__device__ __forceinline__ void combine_tile(
    int tid, int tile, int N, float ts,
    const float* __restrict__ bg, const float* __restrict__ bh,
    const float* __restrict__ bfg, const float* __restrict__ bfh,
    __nv_bfloat16* znx, int znx_stride,
    __nv_bfloat16* zsh, int zsh_stride,
    float* yp, float* hfp, int hoff)
{
    const float* Pb = g_part + (size_t)tile * KS * (128 * 64);
    #pragma unroll
    for (int it = 0; it < 4; it++) {
        int pair = tid + it * 256;
        int b = pair >> 4;
        int jj = pair & 15;
        int j = tile * 16 + jj;
        if (j >= N) continue;
        float4 h4 = make_float4(0.f, 0.f, 0.f, 0.f);
        float4 l4 = make_float4(0.f, 0.f, 0.f, 0.f);
        #pragma unroll
        for (int s = 0; s < KS; s++) {
            float4 a = __ldcg((const float4*)(Pb + (size_t)s * (128 * 64) + b * 64 + jj * 4));
            float4 c = __ldcg((const float4*)(Pb + (size_t)s * (128 * 64) + (b + 64) * 64 + jj * 4));
            h4.x += a.x; h4.y += a.y; h4.z += a.z; h4.w += a.w;
            l4.x += c.x; l4.y += c.y; l4.z += c.z; l4.w += c.w;
        }
        float a0 = h4.x + l4.x;
        float a1 = h4.y + l4.y;
        float a2 = h4.z + l4.z;
        float a3 = h4.w + l4.w;
        float g    = tanhf(a0 + bg[j]);
        float hh   = tanhf(a1 + bh[j]);
        float pre  = (a2 + bfg[j]) + ts * (a3 + bfh[j]);
        float gate = 1.f / (1.f + expf(-pre));
        float o    = g * (1.f - gate) + hh * gate;
        __nv_bfloat16 ohi = __float2bfloat16(o);
        __nv_bfloat16 olo = __float2bfloat16(o - __bfloat162float(ohi));
        if (znx) {
            znx[(size_t)b * znx_stride + j] = ohi;
            znx[(size_t)(b + 64) * znx_stride + j] = olo;
        }
        zsh[(size_t)b * zsh_stride + j] = ohi;
        zsh[(size_t)(b + 64) * zsh_stride + j] = olo;
        if (yp)  yp[(size_t)b * (SEQ * MOTOR) + j] = o;
        if (hfp) hfp[(size_t)b * NUNITS + hoff + j] = o;
    }
}

__global__ void __launch_bounds__(256)
scan_kernel(const float* __restrict__ tsp,
            const float* __restrict__ bg1, const float* __restrict__ bh1,
            const float* __restrict__ bfg1, const float* __restrict__ bfh1,
            const float* __restrict__ bg2, const float* __restrict__ bh2,
            const float* __restrict__ bfg2, const float* __restrict__ bfh2,
            const float* __restrict__ bg3, const float* __restrict__ bh3,
            const float* __restrict__ bfg3, const float* __restrict__ bfh3,
            float* __restrict__ out)
{
    extern __shared__ char smem[];
    const uint32_t sb = s2u32(smem);
    const int tid = threadIdx.x;
    const int bid = blockIdx.x;
    int target = 0;

    for (int s = 0; s < SEQ; s++) {
        const int p = s & 1;
        const float ts = tsp[s];
        float* hfp = (s == SEQ - 1) ? (out + YSZ) : nullptr;

        #pragma unroll 1
        for (int cell = 0; cell < 3; cell++) {
            const __nv_bfloat16 *xp, *hp, *wb;
            int xstr, xch, hstr, hch, wKc, JT, N, hoff;
            __nv_bfloat16 *znx, *zsh;
            int znx_str, zsh_str;
            float* yp;
            if (cell == 0) {
                xp = g_x1 + (size_t)s * 128 * IN_F; xstr = IN_F; xch = XCH1;
                hp = g_z1h[p]; hstr = HPAD1; hch = HCH1;
                wb = g_wb1; wKc = KC1; JT = JT1; N = INTER; hoff = 0;
                znx = g_z2x; znx_str = XPAD2;
                zsh = g_z1h[1 - p]; zsh_str = HPAD1;
                yp = nullptr;
            } else if (cell == 1) {
                xp = g_z2x; xstr = XPAD2; xch = XCH2;
                hp = g_z2h[p]; hstr = HPAD2; hch = HCH2;
                wb = g_wb2; wKc = KC2; JT = JT2; N = CMD; hoff = INTER;
                znx = g_z3x; znx_str = XPAD3;
                zsh = g_z2h[1 - p]; zsh_str = HPAD2;
                yp = nullptr;
            } else {
                xp = g_z3x; xstr = XPAD3; xch = XCH3;
                hp = g_z3h[p]; hstr = HPAD3; hch = HCH3;
                wb = g_wb3; wKc = KC3; JT = JT3; N = MOTOR; hoff = INTER + CMD;
                znx = nullptr; znx_str = 0;
                zsh = g_z3h[1 - p]; zsh_str = HPAD3;
                yp = out + (size_t)s * MOTOR;
            }
            const float* bgc  = (cell == 0) ? bg1  : (cell == 1) ? bg2  : bg3;
            const float* bhc  = (cell == 0) ? bh1  : (cell == 1) ? bh2  : bh3;
            const float* bfgc = (cell == 0) ? bfg1 : (cell == 1) ? bfg2 : bfg3;
            const float* bfhc = (cell == 0) ? bfh1 : (cell == 1) ? bfh2 : bfh3;

            // phase A: split-K partials
            int items = JT * KS;
            for (int it = bid; it < items; it += GRID)
                compute_partial(sb, tid, xp, xstr, xch, hp, hstr, hch,
                                wb, wKc, it / KS, it % KS);
            gbar(bid, tid, ++target);

            // phase B: combine + gating epilogue
            if (bid < JT)
                combine_tile(tid, bid, N, ts, bgc, bhc, bfgc, bfhc,
                             znx, znx_str, zsh, zsh_str, yp, hfp, hoff);
            gbar(bid, tid, ++target);
        }
    }
}

// ---------------- host ----------------
extern "C" void kernel_launch(void* const* d_in, const int* in_sizes, int n_in,
                              void* d_out, int out_size)
{
    const float* x   = (const float*)d_in[0];
    const float* h0  = (const float*)d_in[1];
    const float* ts  = (const float*)d_in[2];
    const float *Wg1=(const float*)d_in[3], *Wh1=(const float*)d_in[4],
                *Wfg1=(const float*)d_in[5], *Wfh1=(const float*)d_in[6],
                *bg1=(const float*)d_in[7], *bh1=(const float*)d_in[8],
                *bfg1=(const float*)d_in[9], *bfh1=(const float*)d_in[10],
                *m1=(const float*)d_in[11];
    const float *Wg2=(const float*)d_in[12], *Wh2=(const float*)d_in[13],
                *Wfg2=(const float*)d_in[14], *Wfh2=(const float*)d_in[15],
                *bg2=(const float*)d_in[16], *bh2=(const float*)d_in[17],
                *bfg2=(const float*)d_in[18], *bfh2=(const float*)d_in[19],
                *m2=(const float*)d_in[20];
    const float *Wg3=(const float*)d_in[21], *Wh3=(const float*)d_in[22],
                *Wfg3=(const float*)d_in[23], *Wfh3=(const float*)d_in[24],
                *bg3=(const float*)d_in[25], *bh3=(const float*)d_in[26],
                *bfg3=(const float*)d_in[27], *bfh3=(const float*)d_in[28],
                *m3=(const float*)d_in[29];
    float* out = (float*)d_out;

    __nv_bfloat16 *wb1, *wb2, *wb3, *x1, *z1h, *z2h, *z3h;
    cudaGetSymbolAddress((void**)&wb1, g_wb1);
    cudaGetSymbolAddress((void**)&wb2, g_wb2);
    cudaGetSymbolAddress((void**)&wb3, g_wb3);
    cudaGetSymbolAddress((void**)&x1,  g_x1);
    cudaGetSymbolAddress((void**)&z1h, g_z1h);
    cudaGetSymbolAddress((void**)&z2h, g_z2h);
    cudaGetSymbolAddress((void**)&z3h, g_z3h);

    cudaFuncSetAttribute(scan_kernel, cudaFuncAttributeMaxDynamicSharedMemorySize,
                         SMEM_TOTAL);

    prep_w_kernel<<<JT1 * 64, 256>>>(Wg1, Wh1, Wfg1, Wfh1, m1, wb1,
                                     INTER, IN_F + INTER, IN_F, IN_F, INTER, KC1);
    prep_w_kernel<<<JT2 * 64, 256>>>(Wg2, Wh2, Wfg2, Wfh2, m2, wb2,
                                     CMD, INTER + CMD, INTER, XPAD2, CMD, KC2);
    prep_w_kernel<<<JT3 * 64, 256>>>(Wg3, Wh3, Wfg3, Wfh3, m3, wb3,
                                     MOTOR, CMD + MOTOR, CMD, XPAD3, MOTOR, KC3);
    prep_x_kernel<<<(BATCH * SEQ * IN_F) / 256, 256>>>(x, x1);
    prep_h0_kernel<<<(BATCH * NUNITS) / 256, 256>>>(h0, z1h, z2h, z3h);

    scan_kernel<<<GRID, 256, SMEM_TOTAL>>>(ts,
        bg1, bh1, bfg1, bfh1, bg2, bh2, bfg2, bfh2, bg3, bh3, bfg3, bfh3, out);

    reset_kernel<<<5, 256>>>();
}

// round 9
// speedup vs baseline: 1.4901x; 1.1672x over previous
#include <cuda_runtime.h>
#include <cuda_bf16.h>
#include <math.h>
#include <stdint.h>

// LiquidNCPNetwork: single persistent kernel, full 32-step scan.
// Runtime-sized co-resident grid (occupancy-queried) so the software grid
// barrier (atomic arrive + release broadcast) is deadlock-free.
// Math identical to R6-R8: bf16 hi/lo split, drop lo*lo term.
//   A rows 0-63 = z_hi, 64-127 = z_lo;  B row n = jj*8 + head*2 + part.
//   out(b,jj,head) = D[b][2h] + D[b][2h+1] + D[b+64][2h].

#define BATCH  64
#define SEQ    32
#define IN_F   512
#define INTER  1229
#define CMD    819
#define MOTOR  512
#define NUNITS 2560
#define YSZ    (BATCH * SEQ * MOTOR)

#define HPAD1 1280
#define KC1   1792
#define XCH1  8
#define HCH1  20
#define XPAD2 1280
#define HPAD2 832
#define KC2   2112
#define XCH2  20
#define HCH2  13
#define XPAD3 832
#define HPAD3 512
#define KC3   1344
#define XCH3  13
#define HCH3  8
#define JT1 77
#define JT2 52
#define JT3 32

#define KS1 3
#define KS2 5
#define KS3 8
#define KSMAX 8
#define MAXGRID 512

__device__ __align__(1024) __nv_bfloat16 g_wb1[(size_t)JT1 * 128 * KC1];
__device__ __align__(1024) __nv_bfloat16 g_wb2[(size_t)JT2 * 128 * KC2];
__device__ __align__(1024) __nv_bfloat16 g_wb3[(size_t)JT3 * 128 * KC3];
__device__ __align__(1024) __nv_bfloat16 g_x1[(size_t)SEQ * 128 * IN_F];
__device__ __align__(1024) __nv_bfloat16 g_z1h[2][128 * HPAD1];
__device__ __align__(1024) __nv_bfloat16 g_z2x[128 * XPAD2];
__device__ __align__(1024) __nv_bfloat16 g_z2h[2][128 * HPAD2];
__device__ __align__(1024) __nv_bfloat16 g_z3x[128 * XPAD3];
__device__ __align__(1024) __nv_bfloat16 g_z3h[2][128 * HPAD3];
// split-K partials: [tile][KSMAX][128][64] f32
__device__ __align__(16) float g_part[(size_t)JT1 * KSMAX * 128 * 64];
// grid barrier state (zeroed by reset_kernel at end of every run)
__device__ int g_arrive;
__device__ volatile int g_release;

#define SW128(o) ((o) ^ (((o) >> 3) & 0x70))
#define STAGE_BYTES 32768
#define SMEM_TOTAL  (3 * STAGE_BYTES)

__device__ __forceinline__ uint32_t s2u32(const void* p) {
    uint32_t a;
    asm("{ .reg .u64 t; cvta.to.shared.u64 t, %1; cvt.u32.u64 %0, t; }" : "=r"(a) : "l"(p));
    return a;
}
__device__ __forceinline__ void cpasync16(uint32_t s, const void* g) {
    asm volatile("cp.async.cg.shared.global [%0], [%1], 16;" :: "r"(s), "l"(g));
}
template<int N> __device__ __forceinline__ void waitgrp() {
    asm volatile("cp.async.wait_group %0;" :: "n"(N) : "memory");
}
__device__ __forceinline__ void ldm_x4(uint32_t& r0, uint32_t& r1, uint32_t& r2,
                                       uint32_t& r3, uint32_t addr) {
    asm volatile("ldmatrix.sync.aligned.m8n8.x4.shared.b16 {%0,%1,%2,%3}, [%4];"
                 : "=r"(r0), "=r"(r1), "=r"(r2), "=r"(r3) : "r"(addr));
}
__device__ __forceinline__ void mma16816(float* c, uint32_t a0, uint32_t a1, uint32_t a2,
                                         uint32_t a3, uint32_t b0, uint32_t b1) {
    asm volatile("mma.sync.aligned.m16n8k16.row.col.f32.bf16.bf16.f32 "
                 "{%0,%1,%2,%3}, {%4,%5,%6,%7}, {%8,%9}, {%0,%1,%2,%3};"
                 : "+f"(c[0]), "+f"(c[1]), "+f"(c[2]), "+f"(c[3])
                 : "r"(a0), "r"(a1), "r"(a2), "r"(a3), "r"(b0), "r"(b1));
}

// grid barrier: atomic arrive counter + release broadcast. Monotonic target;
// counter accumulates across phases (phase k completes at k*nb arrivals).
__device__ __forceinline__ void gbar(int tid, int target, int nb) {
    __syncthreads();
    if (tid == 0) {
        __threadfence();
        int prev = atomicAdd(&g_arrive, 1);
        if (prev == target * nb - 1) {
            g_release = target;
        } else {
            while (g_release < target) { }
            __threadfence();
        }
    }
    __syncthreads();
}

// ---------------- prep kernels ----------------
// merged weight prep: one kernel covers all 3 cells (keeps scan at launch #4)
__global__ void prep_w_all(
    const float* __restrict__ Wg1, const float* __restrict__ Wh1,
    const float* __restrict__ Wfg1, const float* __restrict__ Wfh1,
    const float* __restrict__ M1,
    const float* __restrict__ Wg2, const float* __restrict__ Wh2,
    const float* __restrict__ Wfg2, const float* __restrict__ Wfh2,
    const float* __restrict__ M2,
    const float* __restrict__ Wg3, const float* __restrict__ Wh3,
    const float* __restrict__ Wfg3, const float* __restrict__ Wfh3,
    const float* __restrict__ M3)
{
    int blk = blockIdx.x;
    const float *Wg, *Wh, *Wfg, *Wfh, *M;
    __nv_bfloat16* dst;
    int N, Korig, xvalid, xpad, hvalid, Kc;
    if (blk < JT1 * 64) {
        Wg = Wg1; Wh = Wh1; Wfg = Wfg1; Wfh = Wfh1; M = M1; dst = g_wb1;
        N = INTER; Korig = IN_F + INTER; xvalid = IN_F; xpad = IN_F;
        hvalid = INTER; Kc = KC1;
    } else if (blk < (JT1 + JT2) * 64) {
        blk -= JT1 * 64;
        Wg = Wg2; Wh = Wh2; Wfg = Wfg2; Wfh = Wfh2; M = M2; dst = g_wb2;
        N = CMD; Korig = INTER + CMD; xvalid = INTER; xpad = XPAD2;
        hvalid = CMD; Kc = KC2;
    } else {
        blk -= (JT1 + JT2) * 64;
        Wg = Wg3; Wh = Wh3; Wfg = Wfg3; Wfh = Wfh3; M = M3; dst = g_wb3;
        N = MOTOR; Korig = CMD + MOTOR; xvalid = CMD; xpad = XPAD3;
        hvalid = MOTOR; Kc = KC3;
    }
    int n = blk * 2;
    int loc = n & 127;
    int j = (n >> 7) * 16 + (loc >> 3);
    int t = (loc >> 1) & 3;
    const float* W = (t == 0) ? Wg : (t == 1) ? Wh : (t == 2) ? Wfg : Wfh;
    __nv_bfloat16* d_hi = dst + (size_t)n * Kc;
    __nv_bfloat16* d_lo = d_hi + Kc;
    bool jok = (j < N);
    for (int k = threadIdx.x; k < Kc; k += 256) {
        float v = 0.f;
        if (jok) {
            int kin; bool ok;
            if (k < xpad) { kin = k; ok = (k < xvalid); }
            else { int hk = k - xpad; kin = xvalid + hk; ok = (hk < hvalid); }
            if (ok) v = W[(size_t)j * Korig + kin] * M[(size_t)j * Korig + kin];
        }
        __nv_bfloat16 hi = __float2bfloat16(v);
        d_hi[k] = hi;
        d_lo[k] = __float2bfloat16(v - __bfloat162float(hi));
    }
}

__global__ void prep_x_kernel(const float* __restrict__ x, __nv_bfloat16* __restrict__ dst)
{
    int idx = blockIdx.x * 256 + threadIdx.x;
    int b = idx >> 14, r = idx & 16383, s = r >> 9, f = r & 511;
    float v = x[idx];
    __nv_bfloat16 hi = __float2bfloat16(v);
    size_t base = (size_t)s * 128 * 512;
    dst[base + (size_t)b * 512 + f] = hi;
    dst[base + (size_t)(b + 64) * 512 + f] = __float2bfloat16(v - __bfloat162float(hi));
}

__global__ void prep_h0_kernel(const float* __restrict__ h0, __nv_bfloat16* __restrict__ z1,
                               __nv_bfloat16* __restrict__ z2, __nv_bfloat16* __restrict__ z3)
{
    int idx = blockIdx.x * 256 + threadIdx.x;
    int b = idx / NUNITS, u = idx % NUNITS;
    float v = h0[idx];
    __nv_bfloat16 hi = __float2bfloat16(v);
    __nv_bfloat16 lo = __float2bfloat16(v - __bfloat162float(hi));
    if (u < INTER)            { z1[(size_t)b*HPAD1+u] = hi; z1[(size_t)(b+64)*HPAD1+u] = lo; }
    else if (u < INTER + CMD) { int c = u - INTER;
                                z2[(size_t)b*HPAD2+c] = hi; z2[(size_t)(b+64)*HPAD2+c] = lo; }
    else                      { int c = u - INTER - CMD;
                                z3[(size_t)b*HPAD3+c] = hi; z3[(size_t)(b+64)*HPAD3+c] = lo; }
}

__global__ void reset_kernel() {
    if (threadIdx.x == 0) { g_arrive = 0; g_release = 0; }
}

// ---------------- persistent scan kernel ----------------
__device__ __forceinline__ void compute_partial(
    uint32_t sb, int tid,
    const __nv_bfloat16* xpart, int xstride, int xchunks,
    const __nv_bfloat16* hpart, int hstride, int hchunks,
    const __nv_bfloat16* wbase, int wKc,
    int tile, int split, int ks)
{
    const int lane = tid & 31;
    const int wid  = tid >> 5;
    const int warprow = wid >> 2;
    const int warpcol = wid & 3;
    const int m_warp = warprow * 64;
    const int n_warp = warpcol * 32;
    const int C = xchunks + hchunks;
    const int c0 = (C * split) / ks;
    const int c1 = (C * (split + 1)) / ks;

    float acc[4][4][4];
    #pragma unroll
    for (int mt = 0; mt < 4; mt++)
        #pragma unroll
        for (int nt = 0; nt < 4; nt++)
            #pragma unroll
            for (int i = 0; i < 4; i++) acc[mt][nt][i] = 0.f;

    auto load_stage = [&](int c) {
        uint32_t abase = sb + (uint32_t)(c % 3) * STAGE_BYTES;
        uint32_t bbase = abase + 16384;
        const char* asrc; size_t astr;
        if (c < xchunks) { asrc = (const char*)xpart + (size_t)c * 128; astr = (size_t)xstride * 2; }
        else { asrc = (const char*)hpart + (size_t)(c - xchunks) * 128; astr = (size_t)hstride * 2; }
        const char* bsrc = (const char*)wbase
                         + ((size_t)tile * 128 * wKc + (size_t)c * 64) * 2;
        const size_t bstr = (size_t)wKc * 2;
        #pragma unroll
        for (int i = 0; i < 4; i++) {
            int g = i * 256 + tid;
            int row = g >> 3, col = g & 7;
            uint32_t off = (uint32_t)(row * 128 + col * 16);
            cpasync16(abase + SW128(off), asrc + (size_t)row * astr + col * 16);
            cpasync16(bbase + SW128(off), bsrc + (size_t)row * bstr + col * 16);
        }
        asm volatile("cp.async.commit_group;" ::: "memory");
    };

    load_stage(c0);
    if (c0 + 1 < c1) load_stage(c0 + 1);

    for (int c = c0; c < c1; c++) {
        if (c + 2 < c1) { load_stage(c + 2); waitgrp<2>(); }
        else if (c + 1 < c1) waitgrp<1>();
        else waitgrp<0>();
        __syncthreads();

        uint32_t abase = sb + (uint32_t)(c % 3) * STAGE_BYTES;
        uint32_t bbase = abase + 16384;
        #pragma unroll
        for (int ksi = 0; ksi < 4; ksi++) {
            int kb = ksi * 32 + (lane >> 4) * 16;
            uint32_t af[4][4];
            #pragma unroll
            for (int mt = 0; mt < 4; mt++) {
                uint32_t off = (uint32_t)((m_warp + mt * 16 + (lane & 15)) * 128 + kb);
                ldm_x4(af[mt][0], af[mt][1], af[mt][2], af[mt][3], abase + SW128(off));
            }
            uint32_t bf[4][2];
            #pragma unroll
            for (int np = 0; np < 2; np++) {
                uint32_t off = (uint32_t)((n_warp + np * 16 + (lane & 15)) * 128 + kb);
                uint32_t r0, r1, r2, r3;
                ldm_x4(r0, r1, r2, r3, bbase + SW128(off));
                bf[np * 2][0] = r0; bf[np * 2 + 1][0] = r1;
                bf[np * 2][1] = r2; bf[np * 2 + 1][1] = r3;
            }
            #pragma unroll
            for (int mt = 0; mt < 4; mt++)
                #pragma unroll
                for (int nt = 0; nt < 4; nt++)
                    mma16816(acc[mt][nt], af[mt][0], af[mt][1], af[mt][2], af[mt][3],
                             bf[nt][0], bf[nt][1]);
        }
        __syncthreads();
    }

    float* P = g_part + ((size_t)tile * KSMAX + split) * (128 * 64);
    int hrow = lane >> 2, head = lane & 3;
    #pragma unroll
    for (int mt = 0; mt < 4; mt++) {
        #pragma unroll
        for (int nt = 0; nt < 4; nt++) {
            int col = (warpcol * 4 + nt) * 4 + head;
            int r0 = m_warp + mt * 16 + hrow;
            if (warprow == 0) {
                P[r0 * 64 + col] = acc[mt][nt][0] + acc[mt][nt][1];
                P[(r0 + 8) * 64 + col] = acc[mt][nt][2] + acc[mt][nt][3];
            } else {
                P[r0 * 64 + col] = acc[mt][nt][0];
                P[(r0 + 8) * 64 + col] = acc[mt][nt][2];
            }
        }
    }
}

// combine one quarter-tile (16 b-rows x 16 cols = 256 pairs)
__device__ __forceinline__ void combine_q(
    int tid, int tile, int quarter, int ks, int N, float ts,
    const float* __restrict__ bg, const float* __restrict__ bh,
    const float* __restrict__ bfg, const float* __restrict__ bfh,
    __nv_bfloat16* znx, int znx_stride,
    __nv_bfloat16* zsh, int zsh_stride,
    float* yp, float* hfp, int hoff)
{
    const float* Pb = g_part + (size_t)tile * KSMAX * (128 * 64);
    int pair = quarter * 256 + tid;
    int b = pair >> 4;
    int jj = pair & 15;
    int j = tile * 16 + jj;
    if (j >= N) return;
    float4 h4 = make_float4(0.f, 0.f, 0.f, 0.f);
    float4 l4 = make_float4(0.f, 0.f, 0.f, 0.f);
    for (int s = 0; s < ks; s++) {
        float4 a = __ldcg((const float4*)(Pb + (size_t)s * (128 * 64) + b * 64 + jj * 4));
        float4 c = __ldcg((const float4*)(Pb + (size_t)s * (128 * 64) + (b + 64) * 64 + jj * 4));
        h4.x += a.x; h4.y += a.y; h4.z += a.z; h4.w += a.w;
        l4.x += c.x; l4.y += c.y; l4.z += c.z; l4.w += c.w;
    }
    float a0 = h4.x + l4.x;
    float a1 = h4.y + l4.y;
    float a2 = h4.z + l4.z;
    float a3 = h4.w + l4.w;
    float g    = tanhf(a0 + bg[j]);
    float hh   = tanhf(a1 + bh[j]);
    float pre  = (a2 + bfg[j]) + ts * (a3 + bfh[j]);
    float gate = 1.f / (1.f + expf(-pre));
    float o    = g * (1.f - gate) + hh * gate;
    __nv_bfloat16 ohi = __float2bfloat16(o);
    __nv_bfloat16 olo = __float2bfloat16(o - __bfloat162float(ohi));
    if (znx) {
        znx[(size_t)b * znx_stride + j] = ohi;
        znx[(size_t)(b + 64) * znx_stride + j] = olo;
    }
    zsh[(size_t)b * zsh_stride + j] = ohi;
    zsh[(size_t)(b + 64) * zsh_stride + j] = olo;
    if (yp)  yp[(size_t)b * (SEQ * MOTOR) + j] = o;
    if (hfp) hfp[(size_t)b * NUNITS + hoff + j] = o;
}

__global__ void __launch_bounds__(256, 2)
scan_kernel(int nb, const float* __restrict__ tsp,
            const float* __restrict__ bg1, const float* __restrict__ bh1,
            const float* __restrict__ bfg1, const float* __restrict__ bfh1,
            const float* __restrict__ bg2, const float* __restrict__ bh2,
            const float* __restrict__ bfg2, const float* __restrict__ bfh2,
            const float* __restrict__ bg3, const float* __restrict__ bh3,
            const float* __restrict__ bfg3, const float* __restrict__ bfh3,
            float* __restrict__ out)
{
    extern __shared__ char smem[];
    const uint32_t sb = s2u32(smem);
    const int tid = threadIdx.x;
    const int bid = blockIdx.x;
    int target = 0;

    for (int s = 0; s < SEQ; s++) {
        const int p = s & 1;
        const float ts = tsp[s];
        float* hfp = (s == SEQ - 1) ? (out + YSZ) : nullptr;

        #pragma unroll 1
        for (int cell = 0; cell < 3; cell++) {
            const __nv_bfloat16 *xp, *hp, *wb;
            int xstr, xch, hstr, hch, wKc, JT, KS, N, hoff;
            __nv_bfloat16 *znx, *zsh;
            int znx_str, zsh_str;
            float* yp;
            if (cell == 0) {
                xp = g_x1 + (size_t)s * 128 * IN_F; xstr = IN_F; xch = XCH1;
                hp = g_z1h[p]; hstr = HPAD1; hch = HCH1;
                wb = g_wb1; wKc = KC1; JT = JT1; KS = KS1; N = INTER; hoff = 0;
                znx = g_z2x; znx_str = XPAD2;
                zsh = g_z1h[1 - p]; zsh_str = HPAD1;
                yp = nullptr;
            } else if (cell == 1) {
                xp = g_z2x; xstr = XPAD2; xch = XCH2;
                hp = g_z2h[p]; hstr = HPAD2; hch = HCH2;
                wb = g_wb2; wKc = KC2; JT = JT2; KS = KS2; N = CMD; hoff = INTER;
                znx = g_z3x; znx_str = XPAD3;
                zsh = g_z2h[1 - p]; zsh_str = HPAD2;
                yp = nullptr;
            } else {
                xp = g_z3x; xstr = XPAD3; xch = XCH3;
                hp = g_z3h[p]; hstr = HPAD3; hch = HCH3;
                wb = g_wb3; wKc = KC3; JT = JT3; KS = KS3; N = MOTOR; hoff = INTER + CMD;
                znx = nullptr; znx_str = 0;
                zsh = g_z3h[1 - p]; zsh_str = HPAD3;
                yp = out + (size_t)s * MOTOR;
            }
            const float* bgc  = (cell == 0) ? bg1  : (cell == 1) ? bg2  : bg3;
            const float* bhc  = (cell == 0) ? bh1  : (cell == 1) ? bh2  : bh3;
            const float* bfgc = (cell == 0) ? bfg1 : (cell == 1) ? bfg2 : bfg3;
            const float* bfhc = (cell == 0) ? bfh1 : (cell == 1) ? bfh2 : bfh3;

            // phase A: split-K partials
            int items = JT * KS;
            for (int it = bid; it < items; it += nb)
                compute_partial(sb, tid, xp, xstr, xch, hp, hstr, hch,
                                wb, wKc, it / KS, it % KS, KS);
            gbar(tid, ++target, nb);

            // phase B: combine quarter-tiles + gating epilogue
            int citems = JT * 4;
            for (int it = bid; it < citems; it += nb)
                combine_q(tid, it >> 2, it & 3, KS, N, ts, bgc, bhc, bfgc, bfhc,
                          znx, znx_str, zsh, zsh_str, yp, hfp, hoff);
            gbar(tid, ++target, nb);
        }
    }
}

// ---------------- host ----------------
extern "C" void kernel_launch(void* const* d_in, const int* in_sizes, int n_in,
                              void* d_out, int out_size)
{
    const float* x   = (const float*)d_in[0];
    const float* h0  = (const float*)d_in[1];
    const float* ts  = (const float*)d_in[2];
    const float *Wg1=(const float*)d_in[3], *Wh1=(const float*)d_in[4],
                *Wfg1=(const float*)d_in[5], *Wfh1=(const float*)d_in[6],
                *bg1=(const float*)d_in[7], *bh1=(const float*)d_in[8],
                *bfg1=(const float*)d_in[9], *bfh1=(const float*)d_in[10],
                *m1=(const float*)d_in[11];
    const float *Wg2=(const float*)d_in[12], *Wh2=(const float*)d_in[13],
                *Wfg2=(const float*)d_in[14], *Wfh2=(const float*)d_in[15],
                *bg2=(const float*)d_in[16], *bh2=(const float*)d_in[17],
                *bfg2=(const float*)d_in[18], *bfh2=(const float*)d_in[19],
                *m2=(const float*)d_in[20];
    const float *Wg3=(const float*)d_in[21], *Wh3=(const float*)d_in[22],
                *Wfg3=(const float*)d_in[23], *Wfh3=(const float*)d_in[24],
                *bg3=(const float*)d_in[25], *bh3=(const float*)d_in[26],
                *bfg3=(const float*)d_in[27], *bfh3=(const float*)d_in[28],
                *m3=(const float*)d_in[29];
    float* out = (float*)d_out;

    __nv_bfloat16 *x1, *z1h, *z2h, *z3h;
    cudaGetSymbolAddress((void**)&x1,  g_x1);
    cudaGetSymbolAddress((void**)&z1h, g_z1h);
    cudaGetSymbolAddress((void**)&z2h, g_z2h);
    cudaGetSymbolAddress((void**)&z3h, g_z3h);

    cudaFuncSetAttribute(scan_kernel, cudaFuncAttributeMaxDynamicSharedMemorySize,
                         SMEM_TOTAL);

    // co-resident grid size (deadlock-free barrier by construction)
    int nper = 1, nsm = 148;
    cudaOccupancyMaxActiveBlocksPerMultiprocessor(&nper, scan_kernel, 256, SMEM_TOTAL);
    cudaDeviceGetAttribute(&nsm, cudaDevAttrMultiProcessorCount, 0);
    if (nper < 1) nper = 1;
    int nb = nper * nsm;
    if (nb > MAXGRID) nb = MAXGRID;

    prep_w_all<<<(JT1 + JT2 + JT3) * 64, 256>>>(Wg1, Wh1, Wfg1, Wfh1, m1,
                                                Wg2, Wh2, Wfg2, Wfh2, m2,
                                                Wg3, Wh3, Wfg3, Wfh3, m3);
    prep_x_kernel<<<(BATCH * SEQ * IN_F) / 256, 256>>>(x, x1);
    prep_h0_kernel<<<(BATCH * NUNITS) / 256, 256>>>(h0, z1h, z2h, z3h);

    scan_kernel<<<nb, 256, SMEM_TOTAL>>>(nb, ts,
        bg1, bh1, bfg1, bfh1, bg2, bh2, bfg2, bfh2, bg3, bh3, bfg3, bfh3, out);

    reset_kernel<<<1, 32>>>();
}

// round 12
// speedup vs baseline: 2.0093x; 1.3485x over previous
#include <cuda_runtime.h>
#include <cuda_bf16.h>
#include <math.h>
#include <stdint.h>

// LiquidNCPNetwork: persistent kernel, cells software-pipelined across steps.
// Phase p computes cell1(s=p), cell2(s=p-1), cell3(s=p-2) concurrently
// (they are mutually independent), then one combine phase. 34 phases,
// 68 grid barriers (two-level atomic tree).
// Math identical to R6-R9: bf16 hi/lo split, drop lo*lo term.

#define BATCH  64
#define SEQ    32
#define IN_F   512
#define INTER  1229
#define CMD    819
#define MOTOR  512
#define NUNITS 2560
#define YSZ    (BATCH * SEQ * MOTOR)

#define HPAD1 1280
#define KC1   1792
#define XCH1  8
#define HCH1  20
#define XPAD2 1280
#define HPAD2 832
#define KC2   2112
#define XCH2  20
#define HCH2  13
#define XPAD3 832
#define HPAD3 512
#define KC3   1344
#define XCH3  13
#define HCH3  8
#define JT1 77
#define JT2 52
#define JT3 32

#define KS1 4
#define KS2 5
#define KS3 3
#define I1 (JT1 * KS1)        // 308
#define I2 (JT2 * KS2)        // 260
#define I3 (JT3 * KS3)        // 96
#define SLOT1 0
#define SLOT2 I1
#define SLOT3 (I1 + I2)
#define NSLOTS (I1 + I2 + I3) // 664
#define MAXGRID 512
#define NBSL 16               // barrier tree fan-in slots

__device__ __align__(1024) __nv_bfloat16 g_wb1[(size_t)JT1 * 128 * KC1];
__device__ __align__(1024) __nv_bfloat16 g_wb2[(size_t)JT2 * 128 * KC2];
__device__ __align__(1024) __nv_bfloat16 g_wb3[(size_t)JT3 * 128 * KC3];
__device__ __align__(1024) __nv_bfloat16 g_x1[(size_t)SEQ * 128 * IN_F];
__device__ __align__(1024) __nv_bfloat16 g_z1h[2][128 * HPAD1];
__device__ __align__(1024) __nv_bfloat16 g_z2x[128 * XPAD2];
__device__ __align__(1024) __nv_bfloat16 g_z2h[2][128 * HPAD2];
__device__ __align__(1024) __nv_bfloat16 g_z3x[128 * XPAD3];
__device__ __align__(1024) __nv_bfloat16 g_z3h[2][128 * HPAD3];
// split-K partials: one 128x64 f32 slot per (cell,tile,split)
__device__ __align__(16) float g_part[(size_t)NSLOTS * 128 * 64];
// two-level barrier state (zeroed by reset_kernel)
__device__ int g_arr[NBSL * 32];   // 128B-padded slot counters
__device__ int g_top;
__device__ volatile int g_release;

#define SW128(o) ((o) ^ (((o) >> 3) & 0x70))
#define STAGE_BYTES 32768
#define SMEM_TOTAL  (3 * STAGE_BYTES)

__device__ __forceinline__ uint32_t s2u32(const void* p) {
    uint32_t a;
    asm("{ .reg .u64 t; cvta.to.shared.u64 t, %1; cvt.u32.u64 %0, t; }" : "=r"(a) : "l"(p));
    return a;
}
__device__ __forceinline__ void cpasync16(uint32_t s, const void* g) {
    asm volatile("cp.async.cg.shared.global [%0], [%1], 16;" :: "r"(s), "l"(g));
}
template<int N> __device__ __forceinline__ void waitgrp() {
    asm volatile("cp.async.wait_group %0;" :: "n"(N) : "memory");
}
__device__ __forceinline__ void ldm_x4(uint32_t& r0, uint32_t& r1, uint32_t& r2,
                                       uint32_t& r3, uint32_t addr) {
    asm volatile("ldmatrix.sync.aligned.m8n8.x4.shared.b16 {%0,%1,%2,%3}, [%4];"
                 : "=r"(r0), "=r"(r1), "=r"(r2), "=r"(r3) : "r"(addr));
}
__device__ __forceinline__ void mma16816(float* c, uint32_t a0, uint32_t a1, uint32_t a2,
                                         uint32_t a3, uint32_t b0, uint32_t b1) {
    asm volatile("mma.sync.aligned.m16n8k16.row.col.f32.bf16.bf16.f32 "
                 "{%0,%1,%2,%3}, {%4,%5,%6,%7}, {%8,%9}, {%0,%1,%2,%3};"
                 : "+f"(c[0]), "+f"(c[1]), "+f"(c[2]), "+f"(c[3])
                 : "r"(a0), "r"(a1), "r"(a2), "r"(a3), "r"(b0), "r"(b1));
}

// two-level grid barrier: slot counters (bid mod NBSL) -> top counter.
// Monotonic target; counters accumulate across phases.
__device__ __forceinline__ void gbar(int bid, int tid, int target, int nb) {
    __syncthreads();
    if (tid == 0) {
        __threadfence();
        int slot = bid & (NBSL - 1);
        int cnt = (nb - slot + NBSL - 1) / NBSL;   // #blocks mapping to slot
        int prev = atomicAdd(&g_arr[slot * 32], 1);
        if (prev == target * cnt - 1) {
            int pt = atomicAdd(&g_top, 1);
            if (pt == target * NBSL - 1) g_release = target;
        }
        while (g_release < target) { }
        __threadfence();
    }
    __syncthreads();
}

// ---------------- prep kernels ----------------
__global__ void prep_w_all(
    const float* __restrict__ Wg1, const float* __restrict__ Wh1,
    const float* __restrict__ Wfg1, const float* __restrict__ Wfh1,
    const float* __restrict__ M1,
    const float* __restrict__ Wg2, const float* __restrict__ Wh2,
    const float* __restrict__ Wfg2, const float* __restrict__ Wfh2,
    const float* __restrict__ M2,
    const float* __restrict__ Wg3, const float* __restrict__ Wh3,
    const float* __restrict__ Wfg3, const float* __restrict__ Wfh3,
    const float* __restrict__ M3)
{
    int blk = blockIdx.x;
    const float *Wg, *Wh, *Wfg, *Wfh, *M;
    __nv_bfloat16* dst;
    int N, Korig, xvalid, xpad, hvalid, Kc;
    if (blk < JT1 * 64) {
        Wg = Wg1; Wh = Wh1; Wfg = Wfg1; Wfh = Wfh1; M = M1; dst = g_wb1;
        N = INTER; Korig = IN_F + INTER; xvalid = IN_F; xpad = IN_F;
        hvalid = INTER; Kc = KC1;
    } else if (blk < (JT1 + JT2) * 64) {
        blk -= JT1 * 64;
        Wg = Wg2; Wh = Wh2; Wfg = Wfg2; Wfh = Wfh2; M = M2; dst = g_wb2;
        N = CMD; Korig = INTER + CMD; xvalid = INTER; xpad = XPAD2;
        hvalid = CMD; Kc = KC2;
    } else {
        blk -= (JT1 + JT2) * 64;
        Wg = Wg3; Wh = Wh3; Wfg = Wfg3; Wfh = Wfh3; M = M3; dst = g_wb3;
        N = MOTOR; Korig = CMD + MOTOR; xvalid = CMD; xpad = XPAD3;
        hvalid = MOTOR; Kc = KC3;
    }
    int n = blk * 2;
    int loc = n & 127;
    int j = (n >> 7) * 16 + (loc >> 3);
    int t = (loc >> 1) & 3;
    const float* W = (t == 0) ? Wg : (t == 1) ? Wh : (t == 2) ? Wfg : Wfh;
    __nv_bfloat16* d_hi = dst + (size_t)n * Kc;
    __nv_bfloat16* d_lo = d_hi + Kc;
    bool jok = (j < N);
    for (int k = threadIdx.x; k < Kc; k += 256) {
        float v = 0.f;
        if (jok) {
            int kin; bool ok;
            if (k < xpad) { kin = k; ok = (k < xvalid); }
            else { int hk = k - xpad; kin = xvalid + hk; ok = (hk < hvalid); }
            if (ok) v = W[(size_t)j * Korig + kin] * M[(size_t)j * Korig + kin];
        }
        __nv_bfloat16 hi = __float2bfloat16(v);
        d_hi[k] = hi;
        d_lo[k] = __float2bfloat16(v - __bfloat162float(hi));
    }
}

__global__ void prep_x_kernel(const float* __restrict__ x, __nv_bfloat16* __restrict__ dst)
{
    int idx = blockIdx.x * 256 + threadIdx.x;
    int b = idx >> 14, r = idx & 16383, s = r >> 9, f = r & 511;
    float v = x[idx];
    __nv_bfloat16 hi = __float2bfloat16(v);
    size_t base = (size_t)s * 128 * 512;
    dst[base + (size_t)b * 512 + f] = hi;
    dst[base + (size_t)(b + 64) * 512 + f] = __float2bfloat16(v - __bfloat162float(hi));
}

__global__ void prep_h0_kernel(const float* __restrict__ h0, __nv_bfloat16* __restrict__ z1,
                               __nv_bfloat16* __restrict__ z2, __nv_bfloat16* __restrict__ z3)
{
    int idx = blockIdx.x * 256 + threadIdx.x;
    int b = idx / NUNITS, u = idx % NUNITS;
    float v = h0[idx];
    __nv_bfloat16 hi = __float2bfloat16(v);
    __nv_bfloat16 lo = __float2bfloat16(v - __bfloat162float(hi));
    if (u < INTER)            { z1[(size_t)b*HPAD1+u] = hi; z1[(size_t)(b+64)*HPAD1+u] = lo; }
    else if (u < INTER + CMD) { int c = u - INTER;
                                z2[(size_t)b*HPAD2+c] = hi; z2[(size_t)(b+64)*HPAD2+c] = lo; }
    else                      { int c = u - INTER - CMD;
                                z3[(size_t)b*HPAD3+c] = hi; z3[(size_t)(b+64)*HPAD3+c] = lo; }
}

__global__ void reset_kernel() {
    int i = threadIdx.x;
    if (i < NBSL * 32) g_arr[i] = 0;
    if (i == 0) { g_top = 0; g_release = 0; }
}

// ---------------- persistent scan kernel ----------------
__device__ __forceinline__ void compute_partial(
    uint32_t sb, int tid,
    const __nv_bfloat16* xpart, int xstride, int xchunks,
    const __nv_bfloat16* hpart, int hstride, int hchunks,
    const __nv_bfloat16* wbase, int wKc,
    int tile, int split, int ks, float* P)
{
    const int lane = tid & 31;
    const int wid  = tid >> 5;
    const int warprow = wid >> 2;
    const int warpcol = wid & 3;
    const int m_warp = warprow * 64;
    const int n_warp = warpcol * 32;
    const int C = xchunks + hchunks;
    const int c0 = (C * split) / ks;
    const int c1 = (C * (split + 1)) / ks;

    float acc[4][4][4];
    #pragma unroll
    for (int mt = 0; mt < 4; mt++)
        #pragma unroll
        for (int nt = 0; nt < 4; nt++)
            #pragma unroll
            for (int i = 0; i < 4; i++) acc[mt][nt][i] = 0.f;

    auto load_stage = [&](int c) {
        uint32_t abase = sb + (uint32_t)(c % 3) * STAGE_BYTES;
        uint32_t bbase = abase + 16384;
        const char* asrc; size_t astr;
        if (c < xchunks) { asrc = (const char*)xpart + (size_t)c * 128; astr = (size_t)xstride * 2; }
        else { asrc = (const char*)hpart + (size_t)(c - xchunks) * 128; astr = (size_t)hstride * 2; }
        const char* bsrc = (const char*)wbase
                         + ((size_t)tile * 128 * wKc + (size_t)c * 64) * 2;
        const size_t bstr = (size_t)wKc * 2;
        #pragma unroll
        for (int i = 0; i < 4; i++) {
            int g = i * 256 + tid;
            int row = g >> 3, col = g & 7;
            uint32_t off = (uint32_t)(row * 128 + col * 16);
            cpasync16(abase + SW128(off), asrc + (size_t)row * astr + col * 16);
            cpasync16(bbase + SW128(off), bsrc + (size_t)row * bstr + col * 16);
        }
        asm volatile("cp.async.commit_group;" ::: "memory");
    };

    load_stage(c0);
    if (c0 + 1 < c1) load_stage(c0 + 1);

    for (int c = c0; c < c1; c++) {
        if (c + 2 < c1) { load_stage(c + 2); waitgrp<2>(); }
        else if (c + 1 < c1) waitgrp<1>();
        else waitgrp<0>();
        __syncthreads();

        uint32_t abase = sb + (uint32_t)(c % 3) * STAGE_BYTES;
        uint32_t bbase = abase + 16384;
        #pragma unroll
        for (int ksi = 0; ksi < 4; ksi++) {
            int kb = ksi * 32 + (lane >> 4) * 16;
            uint32_t af[4][4];
            #pragma unroll
            for (int mt = 0; mt < 4; mt++) {
                uint32_t off = (uint32_t)((m_warp + mt * 16 + (lane & 15)) * 128 + kb);
                ldm_x4(af[mt][0], af[mt][1], af[mt][2], af[mt][3], abase + SW128(off));
            }
            uint32_t bf[4][2];
            #pragma unroll
            for (int np = 0; np < 2; np++) {
                uint32_t off = (uint32_t)((n_warp + np * 16 + (lane & 15)) * 128 + kb);
                uint32_t r0, r1, r2, r3;
                ldm_x4(r0, r1, r2, r3, bbase + SW128(off));
                bf[np * 2][0] = r0; bf[np * 2 + 1][0] = r1;
                bf[np * 2][1] = r2; bf[np * 2 + 1][1] = r3;
            }
            #pragma unroll
            for (int mt = 0; mt < 4; mt++)
                #pragma unroll
                for (int nt = 0; nt < 4; nt++)
                    mma16816(acc[mt][nt], af[mt][0], af[mt][1], af[mt][2], af[mt][3],
                             bf[nt][0], bf[nt][1]);
        }
        __syncthreads();
    }

    int hrow = lane >> 2, head = lane & 3;
    #pragma unroll
    for (int mt = 0; mt < 4; mt++) {
        #pragma unroll
        for (int nt = 0; nt < 4; nt++) {
            int col = (warpcol * 4 + nt) * 4 + head;
            int r0 = m_warp + mt * 16 + hrow;
            if (warprow == 0) {
                P[r0 * 64 + col] = acc[mt][nt][0] + acc[mt][nt][1];
                P[(r0 + 8) * 64 + col] = acc[mt][nt][2] + acc[mt][nt][3];
            } else {
                P[r0 * 64 + col] = acc[mt][nt][0];
                P[(r0 + 8) * 64 + col] = acc[mt][nt][2];
            }
        }
    }
}

__device__ __forceinline__ void combine_q(
    int tid, const float* Pb, int tile, int quarter, int ks, int N, float ts,
    const float* __restrict__ bg, const float* __restrict__ bh,
    const float* __restrict__ bfg, const float* __restrict__ bfh,
    __nv_bfloat16* znx, int znx_stride,
    __nv_bfloat16* zsh, int zsh_stride,
    float* yp, float* hfp, int hoff)
{
    int pair = quarter * 256 + tid;
    int b = pair >> 4;
    int jj = pair & 15;
    int j = tile * 16 + jj;
    if (j >= N) return;
    float4 h4 = make_float4(0.f, 0.f, 0.f, 0.f);
    float4 l4 = make_float4(0.f, 0.f, 0.f, 0.f);
    for (int s = 0; s < ks; s++) {
        float4 a = __ldcg((const float4*)(Pb + (size_t)s * (128 * 64) + b * 64 + jj * 4));
        float4 c = __ldcg((const float4*)(Pb + (size_t)s * (128 * 64) + (b + 64) * 64 + jj * 4));
        h4.x += a.x; h4.y += a.y; h4.z += a.z; h4.w += a.w;
        l4.x += c.x; l4.y += c.y; l4.z += c.z; l4.w += c.w;
    }
    float a0 = h4.x + l4.x;
    float a1 = h4.y + l4.y;
    float a2 = h4.z + l4.z;
    float a3 = h4.w + l4.w;
    float g    = tanhf(a0 + bg[j]);
    float hh   = tanhf(a1 + bh[j]);
    float pre  = (a2 + bfg[j]) + ts * (a3 + bfh[j]);
    float gate = 1.f / (1.f + expf(-pre));
    float o    = g * (1.f - gate) + hh * gate;
    __nv_bfloat16 ohi = __float2bfloat16(o);
    __nv_bfloat16 olo = __float2bfloat16(o - __bfloat162float(ohi));
    if (znx) {
        znx[(size_t)b * znx_stride + j] = ohi;
        znx[(size_t)(b + 64) * znx_stride + j] = olo;
    }
    zsh[(size_t)b * zsh_stride + j] = ohi;
    zsh[(size_t)(b + 64) * zsh_stride + j] = olo;
    if (yp)  yp[(size_t)b * (SEQ * MOTOR) + j] = o;
    if (hfp) hfp[(size_t)b * NUNITS + hoff + j] = o;
}

__global__ void __launch_bounds__(256, 2)
scan_kernel(int nb, const float* __restrict__ tsp,
            const float* __restrict__ bg1, const float* __restrict__ bh1,
            const float* __restrict__ bfg1, const float* __restrict__ bfh1,
            const float* __restrict__ bg2, const float* __restrict__ bh2,
            const float* __restrict__ bfg2, const float* __restrict__ bfh2,
            const float* __restrict__ bg3, const float* __restrict__ bh3,
            const float* __restrict__ bfg3, const float* __restrict__ bfh3,
            float* __restrict__ out)
{
    extern __shared__ char smem[];
    const uint32_t sb = s2u32(smem);
    const int tid = threadIdx.x;
    const int bid = blockIdx.x;
    int target = 0;

    for (int p = 0; p < SEQ + 2; p++) {
        const int s1 = p, s2 = p - 1, s3 = p - 2;
        const bool a1 = (s1 < SEQ);
        const bool a2 = (s2 >= 0 && s2 < SEQ);
        const bool a3 = (s3 >= 0 && s3 < SEQ);
        const int n1 = a1 ? I1 : 0;
        const int n2 = a2 ? I2 : 0;
        const int n3 = a3 ? I3 : 0;
        const int total = n1 + n2 + n3;

        // ---- compute phase: all active cells' split-K partials ----
        for (int it = bid; it < total; it += nb) {
            if (it < n1) {
                int tile = it / KS1, split = it % KS1;
                compute_partial(sb, tid,
                    g_x1 + (size_t)s1 * 128 * IN_F, IN_F, XCH1,
                    g_z1h[s1 & 1], HPAD1, HCH1,
                    g_wb1, KC1, tile, split, KS1,
                    g_part + (size_t)(SLOT1 + it) * (128 * 64));
            } else if (it < n1 + n2) {
                int li = it - n1;
                int tile = li / KS2, split = li % KS2;
                compute_partial(sb, tid,
                    g_z2x, XPAD2, XCH2,
                    g_z2h[s2 & 1], HPAD2, HCH2,
                    g_wb2, KC2, tile, split, KS2,
                    g_part + (size_t)(SLOT2 + li) * (128 * 64));
            } else {
                int li = it - n1 - n2;
                int tile = li / KS3, split = li % KS3;
                compute_partial(sb, tid,
                    g_z3x, XPAD3, XCH3,
                    g_z3h[s3 & 1], HPAD3, HCH3,
                    g_wb3, KC3, tile, split, KS3,
                    g_part + (size_t)(SLOT3 + li) * (128 * 64));
            }
        }
        gbar(bid, tid, ++target, nb);

        // ---- combine phase ----
        const int c1n = a1 ? JT1 * 4 : 0;
        const int c2n = a2 ? JT2 * 4 : 0;
        const int c3n = a3 ? JT3 * 4 : 0;
        const int ctotal = c1n + c2n + c3n;
        for (int it = bid; it < ctotal; it += nb) {
            if (it < c1n) {
                int tile = it >> 2, q = it & 3;
                combine_q(tid, g_part + (size_t)(SLOT1 + tile * KS1) * (128 * 64),
                          tile, q, KS1, INTER, tsp[s1], bg1, bh1, bfg1, bfh1,
                          g_z2x, XPAD2, g_z1h[(s1 + 1) & 1], HPAD1,
                          nullptr, (s1 == SEQ - 1) ? (out + YSZ) : nullptr, 0);
            } else if (it < c1n + c2n) {
                int li = it - c1n;
                int tile = li >> 2, q = li & 3;
                combine_q(tid, g_part + (size_t)(SLOT2 + tile * KS2) * (128 * 64),
                          tile, q, KS2, CMD, tsp[s2], bg2, bh2, bfg2, bfh2,
                          g_z3x, XPAD3, g_z2h[(s2 + 1) & 1], HPAD2,
                          nullptr, (s2 == SEQ - 1) ? (out + YSZ) : nullptr, INTER);
            } else {
                int li = it - c1n - c2n;
                int tile = li >> 2, q = li & 3;
                combine_q(tid, g_part + (size_t)(SLOT3 + tile * KS3) * (128 * 64),
                          tile, q, KS3, MOTOR, tsp[s3], bg3, bh3, bfg3, bfh3,
                          nullptr, 0, g_z3h[(s3 + 1) & 1], HPAD3,
                          out + (size_t)s3 * MOTOR,
                          (s3 == SEQ - 1) ? (out + YSZ) : nullptr, INTER + CMD);
            }
        }
        gbar(bid, tid, ++target, nb);
    }
}

// ---------------- host ----------------
extern "C" void kernel_launch(void* const* d_in, const int* in_sizes, int n_in,
                              void* d_out, int out_size)
{
    const float* x   = (const float*)d_in[0];
    const float* h0  = (const float*)d_in[1];
    const float* ts  = (const float*)d_in[2];
    const float *Wg1=(const float*)d_in[3], *Wh1=(const float*)d_in[4],
                *Wfg1=(const float*)d_in[5], *Wfh1=(const float*)d_in[6],
                *bg1=(const float*)d_in[7], *bh1=(const float*)d_in[8],
                *bfg1=(const float*)d_in[9], *bfh1=(const float*)d_in[10],
                *m1=(const float*)d_in[11];
    const float *Wg2=(const float*)d_in[12], *Wh2=(const float*)d_in[13],
                *Wfg2=(const float*)d_in[14], *Wfh2=(const float*)d_in[15],
                *bg2=(const float*)d_in[16], *bh2=(const float*)d_in[17],
                *bfg2=(const float*)d_in[18], *bfh2=(const float*)d_in[19],
                *m2=(const float*)d_in[20];
    const float *Wg3=(const float*)d_in[21], *Wh3=(const float*)d_in[22],
                *Wfg3=(const float*)d_in[23], *Wfh3=(const float*)d_in[24],
                *bg3=(const float*)d_in[25], *bh3=(const float*)d_in[26],
                *bfg3=(const float*)d_in[27], *bfh3=(const float*)d_in[28],
                *m3=(const float*)d_in[29];
    float* out = (float*)d_out;

    __nv_bfloat16 *x1, *z1h, *z2h, *z3h;
    cudaGetSymbolAddress((void**)&x1,  g_x1);
    cudaGetSymbolAddress((void**)&z1h, g_z1h);
    cudaGetSymbolAddress((void**)&z2h, g_z2h);
    cudaGetSymbolAddress((void**)&z3h, g_z3h);

    cudaFuncSetAttribute(scan_kernel, cudaFuncAttributeMaxDynamicSharedMemorySize,
                         SMEM_TOTAL);

    int nper = 1, nsm = 148;
    cudaOccupancyMaxActiveBlocksPerMultiprocessor(&nper, scan_kernel, 256, SMEM_TOTAL);
    cudaDeviceGetAttribute(&nsm, cudaDevAttrMultiProcessorCount, 0);
    if (nper < 1) nper = 1;
    int nb = nper * nsm;
    if (nb > MAXGRID) nb = MAXGRID;

    prep_w_all<<<(JT1 + JT2 + JT3) * 64, 256>>>(Wg1, Wh1, Wfg1, Wfh1, m1,
                                                Wg2, Wh2, Wfg2, Wfh2, m2,
                                                Wg3, Wh3, Wfg3, Wfh3, m3);
    prep_x_kernel<<<(BATCH * SEQ * IN_F) / 256, 256>>>(x, x1);
    prep_h0_kernel<<<(BATCH * NUNITS) / 256, 256>>>(h0, z1h, z2h, z3h);

    scan_kernel<<<nb, 256, SMEM_TOTAL>>>(nb, ts,
        bg1, bh1, bfg1, bfh1, bg2, bh2, bfg2, bfh2, bg3, bh3, bfg3, bfh3, out);

    reset_kernel<<<1, 512>>>();
}